// round 1
// baseline (speedup 1.0000x reference)
#include <cuda_runtime.h>
#include <math.h>

// ---------------- problem constants ----------------
#define B_    4
#define S_    2048
#define D_    2048
#define H_    16
#define DH_   128
#define DFF_  8192
#define MTOK  (B_*S_)          // 8192 rows ("tokens")
#define D3_   (3*D_)           // 6144

// ---------------- scratch (device globals; no allocation allowed) ----------
__device__ float  g_X   [MTOK * D3_];        // QKV output [8192,6144]   201 MB
__device__ float  g_WsmP[8][64][DH_*DH_];    // gram split-K partials     33 MB
__device__ float  g_Wsm [64][DH_*DH_];       // softmax(w) per (b,h)       4 MB
__device__ float  g_A   [MTOK * D_];         // attn out (reshaped)       67 MB
__device__ float  g_R1  [MTOK * D_];         // attn proj + resid         67 MB
__device__ float  g_LN1 [MTOK * D_];         // after global LN1          67 MB
__device__ float  g_H   [MTOK * DFF_];       // gelu(fc)                 268 MB
__device__ float  g_R2  [MTOK * D_];         // ffn proj + resid          67 MB
__device__ double g_part[2048];              // per-block (sum, sumsq)
__device__ float  g_stats[2];                // mean, inv_std

__device__ __forceinline__ float gelu_f(float x) {
    float x3 = x * x * x;
    return 0.5f * x * (1.0f + tanhf(0.7978845608028654f * (x + 0.044715f * x3)));
}

// ---------------- generic NT SGEMM: C[M,N] = alpha*A[M,K]@B[N,K]^T (+bias)(+resid)(gelu) ----
// BM=BN=128, BK=16, 256 threads, 8x8 microtile. All dims multiples of tile sizes.
// MODE 0: flat (gridDim.z==1).  MODE 1: w@V^T batched over z=(b,h), offsets computed inline.
#define BM 128
#define BN 128
#define BK 16

template<int MODE, bool GELU, bool HAS_BIAS, bool HAS_RES>
__global__ __launch_bounds__(256) void gemm_nt(
    const float* __restrict__ A, const float* __restrict__ Bm, float* __restrict__ C,
    const float* __restrict__ bias, const float* __restrict__ resid,
    int K, int lda, int ldb, int ldc, float alpha)
{
    long long offA = 0, offB = 0, offC = 0;
    if (MODE == 1) {
        int z = blockIdx.z; int b = z >> 4; int h = z & 15;
        offA = (long long)z * (DH_ * DH_);                       // w block
        offB = (long long)b * S_ * D3_ + 2 * D_ + (long long)h * DH_;  // V[b, f, h*128+e]
        offC = ((long long)b * S_ + (long long)h * DH_) * D_;    // A rows t=h*128+d
    }
    const float* Ap = A + offA;
    const float* Bp = Bm + offB;
    float*       Cp = C + offC;

    __shared__ float As[BK][BM + 4];
    __shared__ float Bs[BK][BN + 4];

    int tid = threadIdx.x;
    int tx = tid & 15, ty = tid >> 4;
    long long rowBase = (long long)blockIdx.y * BM;
    long long colBase = (long long)blockIdx.x * BN;

    int lr = tid >> 2;          // 0..63
    int lc = (tid & 3) << 2;    // 0,4,8,12

    const float* Aload = Ap + (rowBase + lr) * (long long)lda + lc;
    const float* Bload = Bp + (colBase + lr) * (long long)ldb + lc;

    float acc[8][8];
    #pragma unroll
    for (int i = 0; i < 8; i++)
        #pragma unroll
        for (int j = 0; j < 8; j++) acc[i][j] = 0.0f;

    for (int k0 = 0; k0 < K; k0 += BK) {
        float4 a0 = *(const float4*)(Aload + k0);
        float4 a1 = *(const float4*)(Aload + (long long)64 * lda + k0);
        float4 b0 = *(const float4*)(Bload + k0);
        float4 b1 = *(const float4*)(Bload + (long long)64 * ldb + k0);
        __syncthreads();
        As[lc+0][lr] = a0.x; As[lc+1][lr] = a0.y; As[lc+2][lr] = a0.z; As[lc+3][lr] = a0.w;
        As[lc+0][lr+64] = a1.x; As[lc+1][lr+64] = a1.y; As[lc+2][lr+64] = a1.z; As[lc+3][lr+64] = a1.w;
        Bs[lc+0][lr] = b0.x; Bs[lc+1][lr] = b0.y; Bs[lc+2][lr] = b0.z; Bs[lc+3][lr] = b0.w;
        Bs[lc+0][lr+64] = b1.x; Bs[lc+1][lr+64] = b1.y; Bs[lc+2][lr+64] = b1.z; Bs[lc+3][lr+64] = b1.w;
        __syncthreads();
        #pragma unroll
        for (int kk = 0; kk < BK; kk++) {
            float4 av0 = *(const float4*)&As[kk][ty * 8];
            float4 av1 = *(const float4*)&As[kk][ty * 8 + 4];
            float4 bv0 = *(const float4*)&Bs[kk][tx * 8];
            float4 bv1 = *(const float4*)&Bs[kk][tx * 8 + 4];
            float a[8] = {av0.x, av0.y, av0.z, av0.w, av1.x, av1.y, av1.z, av1.w};
            float b[8] = {bv0.x, bv0.y, bv0.z, bv0.w, bv1.x, bv1.y, bv1.z, bv1.w};
            #pragma unroll
            for (int i = 0; i < 8; i++)
                #pragma unroll
                for (int j = 0; j < 8; j++) acc[i][j] += a[i] * b[j];
        }
    }

    float bcol[8];
    if (HAS_BIAS) {
        #pragma unroll
        for (int j = 0; j < 8; j++) bcol[j] = bias[colBase + tx * 8 + j];
    }
    #pragma unroll
    for (int i = 0; i < 8; i++) {
        long long m = rowBase + ty * 8 + i;
        long long cbase = m * (long long)ldc + colBase + tx * 8;
        float v[8];
        #pragma unroll
        for (int j = 0; j < 8; j++) {
            float t = acc[i][j] * alpha;
            if (HAS_BIAS) t += bcol[j];
            if (HAS_RES)  t += resid[cbase + j];   // resid has same geometry as C (MODE 0 only)
            if (GELU)     t = gelu_f(t);
            v[j] = t;
        }
        *(float4*)&Cp[cbase]     = make_float4(v[0], v[1], v[2], v[3]);
        *(float4*)&Cp[cbase + 4] = make_float4(v[4], v[5], v[6], v[7]);
    }
}

// ---------------- attention gram: per (b,h), split-K over S ----------------
// W_part[split][z][d][e] = sum_{s in split chunk} Q[b,s,h*128+d] * K[b,s,h*128+e]
__global__ __launch_bounds__(256) void attn_gram_kernel()
{
    int z = blockIdx.x;            // 0..63 : b*16+h
    int split = blockIdx.y;        // 0..7
    int b = z >> 4, h = z & 15;
    const float* Qb = g_X + (long long)b * S_ * D3_ + (long long)h * DH_;
    const float* Kb = Qb + D_;

    __shared__ float Qs[32][DH_];
    __shared__ float Ks[32][DH_];

    int tid = threadIdx.x;
    int tx = tid & 15, ty = tid >> 4;
    int r = tid >> 3;              // 0..31
    int c = (tid & 7) << 4;        // 0..112 step 16

    float acc[8][8];
    #pragma unroll
    for (int i = 0; i < 8; i++)
        #pragma unroll
        for (int j = 0; j < 8; j++) acc[i][j] = 0.0f;

    int s_begin = split * 256;
    for (int s0 = s_begin; s0 < s_begin + 256; s0 += 32) {
        __syncthreads();
        long long rowOff = (long long)(s0 + r) * D3_;
        #pragma unroll
        for (int i = 0; i < 4; i++) {
            *(float4*)&Qs[r][c + 4 * i] = *(const float4*)&Qb[rowOff + c + 4 * i];
            *(float4*)&Ks[r][c + 4 * i] = *(const float4*)&Kb[rowOff + c + 4 * i];
        }
        __syncthreads();
        #pragma unroll
        for (int kk = 0; kk < 32; kk++) {
            float4 av0 = *(const float4*)&Qs[kk][ty * 8];
            float4 av1 = *(const float4*)&Qs[kk][ty * 8 + 4];
            float4 bv0 = *(const float4*)&Ks[kk][tx * 8];
            float4 bv1 = *(const float4*)&Ks[kk][tx * 8 + 4];
            float a[8] = {av0.x, av0.y, av0.z, av0.w, av1.x, av1.y, av1.z, av1.w};
            float bb[8] = {bv0.x, bv0.y, bv0.z, bv0.w, bv1.x, bv1.y, bv1.z, bv1.w};
            #pragma unroll
            for (int i = 0; i < 8; i++)
                #pragma unroll
                for (int j = 0; j < 8; j++) acc[i][j] += a[i] * bb[j];
        }
    }
    #pragma unroll
    for (int i = 0; i < 8; i++) {
        int d = ty * 8 + i;
        *(float4*)&g_WsmP[split][z][d * DH_ + tx * 8]     = make_float4(acc[i][0], acc[i][1], acc[i][2], acc[i][3]);
        *(float4*)&g_WsmP[split][z][d * DH_ + tx * 8 + 4] = make_float4(acc[i][4], acc[i][5], acc[i][6], acc[i][7]);
    }
}

// ---------------- softmax over e (row length 128), folds split-K sum + 1/sqrt(S) -------
__global__ void softmax_kernel()
{
    int row = blockIdx.x;          // 0..8191 : z*128+d
    int z = row >> 7, d = row & 127;
    int e = threadIdx.x;           // 0..127
    float v = 0.0f;
    #pragma unroll
    for (int p = 0; p < 8; p++) v += g_WsmP[p][z][d * DH_ + e];
    v *= 0.022097086912079608f;    // 1/sqrt(2048)

    __shared__ float red[128];
    red[e] = v; __syncthreads();
    for (int off = 64; off; off >>= 1) { if (e < off) red[e] = fmaxf(red[e], red[e + off]); __syncthreads(); }
    float mx = red[0];
    __syncthreads();
    float ex = expf(v - mx);
    red[e] = ex; __syncthreads();
    for (int off = 64; off; off >>= 1) { if (e < off) red[e] += red[e + off]; __syncthreads(); }
    g_Wsm[z][d * DH_ + e] = ex / red[0];
}

// ---------------- global layernorm: two-stage deterministic fp64 reduction -------------
__global__ void reduce1_kernel(const float* __restrict__ x, long long n)
{
    int t = threadIdx.x;
    double s = 0.0, ss = 0.0;
    for (long long i = (long long)blockIdx.x * blockDim.x + t; i < n;
         i += (long long)gridDim.x * blockDim.x) {
        double v = (double)x[i]; s += v; ss += v * v;
    }
    __shared__ double shs[256], shq[256];
    shs[t] = s; shq[t] = ss; __syncthreads();
    for (int off = 128; off; off >>= 1) {
        if (t < off) { shs[t] += shs[t + off]; shq[t] += shq[t + off]; }
        __syncthreads();
    }
    if (t == 0) { g_part[2 * blockIdx.x] = shs[0]; g_part[2 * blockIdx.x + 1] = shq[0]; }
}

__global__ void reduce2_kernel(double n)
{
    int t = threadIdx.x;
    double s = 0.0, ss = 0.0;
    for (int i = t; i < 1024; i += 256) { s += g_part[2 * i]; ss += g_part[2 * i + 1]; }
    __shared__ double shs[256], shq[256];
    shs[t] = s; shq[t] = ss; __syncthreads();
    for (int off = 128; off; off >>= 1) {
        if (t < off) { shs[t] += shs[t + off]; shq[t] += shq[t + off]; }
        __syncthreads();
    }
    if (t == 0) {
        double mean = shs[0] / n;
        double var  = (shq[0] - n * mean * mean) / (n - 1.0);   // unbiased (ddof=1)
        g_stats[0] = (float)mean;
        g_stats[1] = (float)(1.0 / sqrt(var + 1e-12));
    }
}

__global__ void ln_apply_kernel(const float* __restrict__ x, const float* __restrict__ w,
                                const float* __restrict__ bb, float* __restrict__ y, long long n)
{
    float mean = g_stats[0], inv = g_stats[1];
    for (long long i = (long long)blockIdx.x * blockDim.x + threadIdx.x; i < n;
         i += (long long)gridDim.x * blockDim.x) {
        int col = (int)(i & (D_ - 1));
        y[i] = (x[i] - mean) * inv * w[col] + bb[col];
    }
}

// ---------------- launcher ----------------
extern "C" void kernel_launch(void* const* d_in, const int* in_sizes, int n_in,
                              void* d_out, int out_size)
{
    const float* x      = (const float*)d_in[0];
    const float* W1_w   = (const float*)d_in[1];
    const float* W1_b   = (const float*)d_in[2];
    const float* W2_w   = (const float*)d_in[3];
    const float* W2_b   = (const float*)d_in[4];
    const float* fc_w   = (const float*)d_in[5];
    const float* fc_b   = (const float*)d_in[6];
    const float* proj_w = (const float*)d_in[7];
    const float* proj_b = (const float*)d_in[8];
    const float* ln1_w  = (const float*)d_in[9];
    const float* ln1_b  = (const float*)d_in[10];
    const float* ln2_w  = (const float*)d_in[11];
    const float* ln2_b  = (const float*)d_in[12];
    float* out = (float*)d_out;

    float *pX, *pWsm, *pA, *pR1, *pLN1, *pH, *pR2;
    cudaGetSymbolAddress((void**)&pX,   g_X);
    cudaGetSymbolAddress((void**)&pWsm, g_Wsm);
    cudaGetSymbolAddress((void**)&pA,   g_A);
    cudaGetSymbolAddress((void**)&pR1,  g_R1);
    cudaGetSymbolAddress((void**)&pLN1, g_LN1);
    cudaGetSymbolAddress((void**)&pH,   g_H);
    cudaGetSymbolAddress((void**)&pR2,  g_R2);

    const long long nLN = (long long)MTOK * D_;   // 16,777,216

    // 1) QKV: g_X = x @ W1^T + W1_b        [8192,6144]
    gemm_nt<0, false, true, false><<<dim3(D3_ / BN, MTOK / BM, 1), 256>>>(
        x, W1_w, pX, W1_b, nullptr, D_, D_, D_, D3_, 1.0f);

    // 2) gram partials (split-K=8), 3) softmax (folds partial sum + scale)
    attn_gram_kernel<<<dim3(64, 8), 256>>>();
    softmax_kernel<<<64 * DH_, 128>>>();

    // 4) A[b, h*128+d, f] = w @ V^T   (batched over 64 (b,h))
    gemm_nt<1, false, false, false><<<dim3(D_ / BN, 1, 64), 256>>>(
        pWsm, pX, pA, nullptr, nullptr, DH_, DH_, D3_, D_, 1.0f);

    // 5) R1 = A @ W2^T + W2_b + x
    gemm_nt<0, false, true, true><<<dim3(D_ / BN, MTOK / BM, 1), 256>>>(
        pA, W2_w, pR1, W2_b, x, D_, D_, D_, D_, 1.0f);

    // 6) global LN1 -> g_LN1
    reduce1_kernel<<<1024, 256>>>(pR1, nLN);
    reduce2_kernel<<<1, 256>>>((double)nLN);
    ln_apply_kernel<<<8192, 256>>>(pR1, ln1_w, ln1_b, pLN1, nLN);

    // 7) H = gelu(LN1 @ fc^T + fc_b)       [8192,8192]
    gemm_nt<0, true, true, false><<<dim3(DFF_ / BN, MTOK / BM, 1), 256>>>(
        pLN1, fc_w, pH, fc_b, nullptr, D_, D_, D_, DFF_, 1.0f);

    // 8) R2 = H @ proj^T + proj_b + LN1
    gemm_nt<0, false, true, true><<<dim3(D_ / BN, MTOK / BM, 1), 256>>>(
        pH, proj_w, pR2, proj_b, pLN1, DFF_, DFF_, DFF_, D_, 1.0f);

    // 9) global LN2 -> out
    reduce1_kernel<<<1024, 256>>>(pR2, nLN);
    reduce2_kernel<<<1, 256>>>((double)nLN);
    ln_apply_kernel<<<8192, 256>>>(pR2, ln2_w, ln2_b, out, nLN);
}

// round 5
// speedup vs baseline: 2.1879x; 2.1879x over previous
#include <cuda_runtime.h>
#include <cuda_bf16.h>
#include <math.h>
#include <stdint.h>

// ---------------- problem constants ----------------
#define B_    4
#define S_    2048
#define D_    2048
#define H_    16
#define DH_   128
#define DFF_  8192
#define MTOK  (B_*S_)          // 8192
#define D3_   (3*D_)           // 6144

// ---------------- scratch (device globals) ----------------
__device__ float          g_X    [(size_t)MTOK * D3_];       // QKV out fp32
__device__ float          g_WsmP [8][64][DH_*DH_];           // gram split-K partials
__device__ float          g_Wsm  [64][DH_*DH_];              // softmax(w)
__device__ float          g_A    [(size_t)MTOK * D_];        // attn out fp32
__device__ float          g_R1   [(size_t)MTOK * D_];
__device__ float          g_LN1  [(size_t)MTOK * D_];
__device__ float          g_R2   [(size_t)MTOK * D_];
__device__ __nv_bfloat16  g_xhl  [(size_t)MTOK * 2*D_];      // hi|lo along K
__device__ __nv_bfloat16  g_W1hl [(size_t)D3_  * 2*D_];
__device__ __nv_bfloat16  g_W2hl [(size_t)D_   * 2*D_];
__device__ __nv_bfloat16  g_fchl [(size_t)DFF_ * 2*D_];
__device__ __nv_bfloat16  g_pjhl [(size_t)D_   * 2*DFF_];
__device__ __nv_bfloat16  g_Ahl  [(size_t)MTOK * 2*D_];
__device__ __nv_bfloat16  g_L1hl [(size_t)MTOK * 2*D_];
__device__ __nv_bfloat16  g_Hhl  [(size_t)MTOK * 2*DFF_];
__device__ double         g_part [2048];
__device__ float          g_stats[2];

__device__ __forceinline__ float gelu_f(float x) {
    float x3 = x * x * x;
    return 0.5f * x * (1.0f + tanhf(0.7978845608028654f * (x + 0.044715f * x3)));
}

// ================= baseline-PTX helpers (compile under compute_103) =================
__device__ __forceinline__ uint32_t smem_u32(const void* p) {
    uint32_t a;
    asm("{ .reg .u64 t; cvta.to.shared.u64 t, %1; cvt.u32.u64 %0, t; }" : "=r"(a) : "l"(p));
    return a;
}
__device__ __forceinline__ void cp16(uint32_t s, const void* g) {
    asm volatile("cp.async.cg.shared.global [%0], [%1], 16;" :: "r"(s), "l"(g));
}
#define CP_COMMIT() asm volatile("cp.async.commit_group;" ::: "memory")
template<int N> __device__ __forceinline__ void cp_wait() {
    asm volatile("cp.async.wait_group %0;" :: "n"(N) : "memory");
}
__device__ __forceinline__ uint32_t swz128(uint32_t off) { return off ^ ((off >> 3) & 0x70); }

#define LDSM4(r, addr) \
    asm volatile("ldmatrix.sync.aligned.m8n8.x4.shared.b16 {%0,%1,%2,%3}, [%4];" \
        : "=r"((r)[0]), "=r"((r)[1]), "=r"((r)[2]), "=r"((r)[3]) : "r"(addr))

#define MMA16816(c, a, b0, b1) \
    asm volatile("mma.sync.aligned.m16n8k16.row.col.f32.bf16.bf16.f32 " \
        "{%0,%1,%2,%3},{%4,%5,%6,%7},{%8,%9},{%0,%1,%2,%3};" \
        : "+f"((c)[0]), "+f"((c)[1]), "+f"((c)[2]), "+f"((c)[3]) \
        : "r"((a)[0]), "r"((a)[1]), "r"((a)[2]), "r"((a)[3]), "r"(b0), "r"(b1))

// ================= mma.sync GEMM: C[M,N] = A[M,2K]hl ⊛ B[N,2K]hl (3x bf16 split) ======
// Tile 128x128, K-step 64, 3-stage cp.async pipeline, 8 warps (4M x 2N), warp tile 32x64.
#define NS          3
#define STAGE_BYTES 32768            // A 128x64x2 = 16K, B 128x64x2 = 16K
#define TCG_SMEM    (NS * STAGE_BYTES)

__device__ __forceinline__ void load_tile(
    const __nv_bfloat16* __restrict__ A, const __nv_bfloat16* __restrict__ Bw,
    uint32_t tA, uint32_t tB, long long rowA0, long long rowB0,
    long long ldg2, long long kA, long long kB, int tid)
{
    #pragma unroll
    for (int i = 0; i < 4; i++) {                       // A: 1024 x 16B chunks
        int q = tid + 256 * i; int r = q >> 3, c = q & 7;
        cp16(tA + swz128(r * 128 + c * 16), A + (rowA0 + r) * ldg2 + kA + c * 8);
    }
    #pragma unroll
    for (int i = 0; i < 4; i++) {                       // B: 1024 x 16B chunks
        int q = tid + 256 * i; int r = q >> 3, c = q & 7;
        cp16(tB + swz128(r * 128 + c * 16), Bw + (rowB0 + r) * ldg2 + kB + c * 8);
    }
}

template<bool GELU, bool RES, bool HILO>
__global__ __launch_bounds__(256, 2) void mma_gemm(
    const __nv_bfloat16* __restrict__ A, const __nv_bfloat16* __restrict__ Bw,
    int K, const float* __restrict__ bias, const float* __restrict__ resid,
    float* __restrict__ Cf, __nv_bfloat16* __restrict__ Chl, int N)
{
    extern __shared__ char smem[];
    const uint32_t tiles = smem_u32(smem);
    const int tid  = threadIdx.x;
    const int wid  = tid >> 5, lane = tid & 31;
    const int wm   = wid >> 1, wn = wid & 1;            // 4 x 2 warp grid

    const long long ldg2  = 2LL * K;
    const long long rowA0 = (long long)blockIdx.y * 128;
    const long long rowB0 = (long long)blockIdx.x * 128;
    const int kst   = K >> 6;
    const int total = 3 * kst;

    float acc[2][8][4];
    #pragma unroll
    for (int i = 0; i < 2; i++)
        #pragma unroll
        for (int j = 0; j < 8; j++)
            #pragma unroll
            for (int q = 0; q < 4; q++) acc[i][j][q] = 0.0f;

    // seg -> (kA, kB): 0: hi*hi, 1: hi*lo, 2: lo*hi
    auto seg_off = [&](int s, long long& kA, long long& kB) {
        int seg = s / kst;
        long long kk = (long long)(s - seg * kst) << 6;
        kA = kk + (seg == 2 ? K : 0);
        kB = kk + (seg == 1 ? K : 0);
    };

    // prologue: stages 0,1
    for (int s = 0; s < 2; s++) {
        long long kA, kB; seg_off(s, kA, kB);
        load_tile(A, Bw, tiles + s * STAGE_BYTES, tiles + s * STAGE_BYTES + 16384,
                  rowA0, rowB0, ldg2, kA, kB, tid);
        CP_COMMIT();
    }

    for (int m = 0; m < total; m++) {
        cp_wait<1>();
        __syncthreads();
        const int s = m + 2;
        if (s < total) {
            long long kA, kB; seg_off(s, kA, kB);
            const int slot = s % NS;
            load_tile(A, Bw, tiles + slot * STAGE_BYTES, tiles + slot * STAGE_BYTES + 16384,
                      rowA0, rowB0, ldg2, kA, kB, tid);
        }
        CP_COMMIT();

        const uint32_t Asm = tiles + (m % NS) * STAGE_BYTES;
        const uint32_t Bsm = Asm + 16384;
        #pragma unroll
        for (int kk = 0; kk < 4; kk++) {
            uint32_t af[2][4];
            #pragma unroll
            for (int mi = 0; mi < 2; mi++) {
                uint32_t addr = Asm + swz128((wm * 32 + mi * 16 + (lane & 15)) * 128
                                             + kk * 32 + (lane >> 4) * 16);
                LDSM4(af[mi], addr);
            }
            uint32_t bfr[4][4];
            #pragma unroll
            for (int nj = 0; nj < 4; nj++) {
                uint32_t addr = Bsm + swz128((wn * 64 + nj * 16 + (lane & 15)) * 128
                                             + kk * 32 + (lane >> 4) * 16);
                LDSM4(bfr[nj], addr);
            }
            #pragma unroll
            for (int mi = 0; mi < 2; mi++)
                #pragma unroll
                for (int nj = 0; nj < 4; nj++) {
                    MMA16816(acc[mi][2*nj],   af[mi], bfr[nj][0], bfr[nj][2]);
                    MMA16816(acc[mi][2*nj+1], af[mi], bfr[nj][1], bfr[nj][3]);
                }
        }
        __syncthreads();
    }

    // epilogue
    const long long rowT = rowA0 + wm * 32;
    const long long colT = rowB0 + wn * 64;
    #pragma unroll
    for (int mi = 0; mi < 2; mi++) {
        #pragma unroll
        for (int n8 = 0; n8 < 8; n8++) {
            const long long col = colT + n8 * 8 + (lane & 3) * 2;
            const float b0 = bias[col], b1 = bias[col + 1];
            #pragma unroll
            for (int h = 0; h < 2; h++) {
                const long long row = rowT + mi * 16 + (lane >> 2) + h * 8;
                float v0 = acc[mi][n8][2*h]     + b0;
                float v1 = acc[mi][n8][2*h + 1] + b1;
                if (RES) {
                    const float2 rv = *(const float2*)(resid + row * N + col);
                    v0 += rv.x; v1 += rv.y;
                }
                if (GELU) { v0 = gelu_f(v0); v1 = gelu_f(v1); }
                if (HILO) {
                    __nv_bfloat16 h0 = __float2bfloat16(v0);
                    __nv_bfloat16 h1 = __float2bfloat16(v1);
                    __nv_bfloat16 l0 = __float2bfloat16(v0 - __bfloat162float(h0));
                    __nv_bfloat16 l1 = __float2bfloat16(v1 - __bfloat162float(h1));
                    *(__nv_bfloat162*)(Chl + row * 2LL * N + col)     = __nv_bfloat162(h0, h1);
                    *(__nv_bfloat162*)(Chl + row * 2LL * N + N + col) = __nv_bfloat162(l0, l1);
                } else {
                    *(float2*)(Cf + row * N + col) = make_float2(v0, v1);
                }
            }
        }
    }
}

// ================= fp32 -> hi/lo bf16 conversion =================
__global__ void convert_hl(const float* __restrict__ src, __nv_bfloat16* __restrict__ dst,
                           long long n, int logC)
{
    const long long C = 1LL << logC;
    for (long long i = (long long)blockIdx.x * blockDim.x + threadIdx.x; i < n;
         i += (long long)gridDim.x * blockDim.x) {
        long long r = i >> logC, c = i & (C - 1);
        float v = src[i];
        __nv_bfloat16 hi = __float2bfloat16(v);
        __nv_bfloat16 lo = __float2bfloat16(v - __bfloat162float(hi));
        long long base = (r << (logC + 1)) + c;
        dst[base] = hi; dst[base + C] = lo;
    }
}

// ================= SIMT pieces (known-correct from round 1) =================
#define BM 128
#define BN 128

__global__ __launch_bounds__(256) void wvT_kernel(const float* __restrict__ Wsm,
                                                  const float* __restrict__ X,
                                                  float* __restrict__ C)
{
    int z = blockIdx.z; int b = z >> 4; int h = z & 15;
    const float* Ap = Wsm + (long long)z * (DH_ * DH_);
    const float* Bp = X + (long long)b * S_ * D3_ + 2 * D_ + (long long)h * DH_;
    float*       Cp = C + ((long long)b * S_ + (long long)h * DH_) * D_;

    __shared__ float As[16][BM + 4];
    __shared__ float Bs[16][BN + 4];
    int tid = threadIdx.x, tx = tid & 15, ty = tid >> 4;
    long long colBase = (long long)blockIdx.x * BN;
    int lr = tid >> 2, lc = (tid & 3) << 2;
    const float* Aload = Ap + lr * DH_ + lc;
    const float* Bload = Bp + (colBase + lr) * (long long)D3_ + lc;

    float acc[8][8];
    #pragma unroll
    for (int i = 0; i < 8; i++) {
        #pragma unroll
        for (int j = 0; j < 8; j++) acc[i][j] = 0.0f;
    }

    for (int k0 = 0; k0 < DH_; k0 += 16) {
        float4 a0 = *(const float4*)(Aload + k0);
        float4 a1 = *(const float4*)(Aload + 64 * DH_ + k0);
        float4 b0 = *(const float4*)(Bload + k0);
        float4 b1 = *(const float4*)(Bload + 64LL * D3_ + k0);
        __syncthreads();
        As[lc+0][lr] = a0.x; As[lc+1][lr] = a0.y; As[lc+2][lr] = a0.z; As[lc+3][lr] = a0.w;
        As[lc+0][lr+64] = a1.x; As[lc+1][lr+64] = a1.y; As[lc+2][lr+64] = a1.z; As[lc+3][lr+64] = a1.w;
        Bs[lc+0][lr] = b0.x; Bs[lc+1][lr] = b0.y; Bs[lc+2][lr] = b0.z; Bs[lc+3][lr] = b0.w;
        Bs[lc+0][lr+64] = b1.x; Bs[lc+1][lr+64] = b1.y; Bs[lc+2][lr+64] = b1.z; Bs[lc+3][lr+64] = b1.w;
        __syncthreads();
        #pragma unroll
        for (int kk = 0; kk < 16; kk++) {
            float4 av0 = *(const float4*)&As[kk][ty * 8];
            float4 av1 = *(const float4*)&As[kk][ty * 8 + 4];
            float4 bv0 = *(const float4*)&Bs[kk][tx * 8];
            float4 bv1 = *(const float4*)&Bs[kk][tx * 8 + 4];
            float a[8] = {av0.x, av0.y, av0.z, av0.w, av1.x, av1.y, av1.z, av1.w};
            float bb[8] = {bv0.x, bv0.y, bv0.z, bv0.w, bv1.x, bv1.y, bv1.z, bv1.w};
            #pragma unroll
            for (int i = 0; i < 8; i++)
                #pragma unroll
                for (int j = 0; j < 8; j++) acc[i][j] += a[i] * bb[j];
        }
    }
    #pragma unroll
    for (int i = 0; i < 8; i++) {
        long long cbase = (long long)(ty * 8 + i) * D_ + colBase + tx * 8;
        *(float4*)&Cp[cbase]     = make_float4(acc[i][0], acc[i][1], acc[i][2], acc[i][3]);
        *(float4*)&Cp[cbase + 4] = make_float4(acc[i][4], acc[i][5], acc[i][6], acc[i][7]);
    }
}

__global__ __launch_bounds__(256) void attn_gram_kernel()
{
    int z = blockIdx.x, split = blockIdx.y;
    int b = z >> 4, h = z & 15;
    const float* Qb = g_X + (long long)b * S_ * D3_ + (long long)h * DH_;
    const float* Kb = Qb + D_;
    __shared__ float Qs[32][DH_];
    __shared__ float Ks[32][DH_];
    int tid = threadIdx.x, tx = tid & 15, ty = tid >> 4;
    int r = tid >> 3, c = (tid & 7) << 4;
    float acc[8][8];
    #pragma unroll
    for (int i = 0; i < 8; i++) {
        #pragma unroll
        for (int j = 0; j < 8; j++) acc[i][j] = 0.0f;
    }
    int s_begin = split * 256;
    for (int s0 = s_begin; s0 < s_begin + 256; s0 += 32) {
        __syncthreads();
        long long rowOff = (long long)(s0 + r) * D3_;
        #pragma unroll
        for (int i = 0; i < 4; i++) {
            *(float4*)&Qs[r][c + 4*i] = *(const float4*)&Qb[rowOff + c + 4*i];
            *(float4*)&Ks[r][c + 4*i] = *(const float4*)&Kb[rowOff + c + 4*i];
        }
        __syncthreads();
        #pragma unroll
        for (int kk = 0; kk < 32; kk++) {
            float4 av0 = *(const float4*)&Qs[kk][ty*8];
            float4 av1 = *(const float4*)&Qs[kk][ty*8+4];
            float4 bv0 = *(const float4*)&Ks[kk][tx*8];
            float4 bv1 = *(const float4*)&Ks[kk][tx*8+4];
            float a[8] = {av0.x,av0.y,av0.z,av0.w,av1.x,av1.y,av1.z,av1.w};
            float bb[8] = {bv0.x,bv0.y,bv0.z,bv0.w,bv1.x,bv1.y,bv1.z,bv1.w};
            #pragma unroll
            for (int i = 0; i < 8; i++)
                #pragma unroll
                for (int j = 0; j < 8; j++) acc[i][j] += a[i] * bb[j];
        }
    }
    #pragma unroll
    for (int i = 0; i < 8; i++) {
        int d = ty * 8 + i;
        *(float4*)&g_WsmP[split][z][d*DH_ + tx*8]   = make_float4(acc[i][0],acc[i][1],acc[i][2],acc[i][3]);
        *(float4*)&g_WsmP[split][z][d*DH_ + tx*8+4] = make_float4(acc[i][4],acc[i][5],acc[i][6],acc[i][7]);
    }
}

__global__ void softmax_kernel()
{
    int row = blockIdx.x;
    int z = row >> 7, d = row & 127;
    int e = threadIdx.x;
    float v = 0.0f;
    #pragma unroll
    for (int p = 0; p < 8; p++) v += g_WsmP[p][z][d*DH_ + e];
    v *= 0.022097086912079608f;
    __shared__ float red[128];
    red[e] = v; __syncthreads();
    for (int off = 64; off; off >>= 1) { if (e < off) red[e] = fmaxf(red[e], red[e+off]); __syncthreads(); }
    float mx = red[0];
    __syncthreads();
    float ex = expf(v - mx);
    red[e] = ex; __syncthreads();
    for (int off = 64; off; off >>= 1) { if (e < off) red[e] += red[e+off]; __syncthreads(); }
    g_Wsm[z][d*DH_ + e] = ex / red[0];
}

__global__ void reduce1_kernel(const float* __restrict__ x, long long n)
{
    int t = threadIdx.x;
    double s = 0.0, ss = 0.0;
    for (long long i = (long long)blockIdx.x * blockDim.x + t; i < n;
         i += (long long)gridDim.x * blockDim.x) {
        double v = (double)x[i]; s += v; ss += v * v;
    }
    __shared__ double shs[256], shq[256];
    shs[t] = s; shq[t] = ss; __syncthreads();
    for (int off = 128; off; off >>= 1) {
        if (t < off) { shs[t] += shs[t+off]; shq[t] += shq[t+off]; }
        __syncthreads();
    }
    if (t == 0) { g_part[2*blockIdx.x] = shs[0]; g_part[2*blockIdx.x+1] = shq[0]; }
}

__global__ void reduce2_kernel(double n)
{
    int t = threadIdx.x;
    double s = 0.0, ss = 0.0;
    for (int i = t; i < 1024; i += 256) { s += g_part[2*i]; ss += g_part[2*i+1]; }
    __shared__ double shs[256], shq[256];
    shs[t] = s; shq[t] = ss; __syncthreads();
    for (int off = 128; off; off >>= 1) {
        if (t < off) { shs[t] += shs[t+off]; shq[t] += shq[t+off]; }
        __syncthreads();
    }
    if (t == 0) {
        double mean = shs[0] / n;
        double var  = (shq[0] - n * mean * mean) / (n - 1.0);
        g_stats[0] = (float)mean;
        g_stats[1] = (float)(1.0 / sqrt(var + 1e-12));
    }
}

__global__ void ln_apply_kernel(const float* __restrict__ x, const float* __restrict__ w,
                                const float* __restrict__ bb, float* __restrict__ y, long long n)
{
    float mean = g_stats[0], inv = g_stats[1];
    for (long long i = (long long)blockIdx.x * blockDim.x + threadIdx.x; i < n;
         i += (long long)gridDim.x * blockDim.x) {
        int col = (int)(i & (D_ - 1));
        y[i] = (x[i] - mean) * inv * w[col] + bb[col];
    }
}

// ================= launcher =================
extern "C" void kernel_launch(void* const* d_in, const int* in_sizes, int n_in,
                              void* d_out, int out_size)
{
    const float* x      = (const float*)d_in[0];
    const float* W1_w   = (const float*)d_in[1];
    const float* W1_b   = (const float*)d_in[2];
    const float* W2_w   = (const float*)d_in[3];
    const float* W2_b   = (const float*)d_in[4];
    const float* fc_w   = (const float*)d_in[5];
    const float* fc_b   = (const float*)d_in[6];
    const float* proj_w = (const float*)d_in[7];
    const float* proj_b = (const float*)d_in[8];
    const float* ln1_w  = (const float*)d_in[9];
    const float* ln1_b  = (const float*)d_in[10];
    const float* ln2_w  = (const float*)d_in[11];
    const float* ln2_b  = (const float*)d_in[12];
    float* out = (float*)d_out;

    float *pX, *pWsm, *pA, *pR1, *pLN1, *pR2;
    __nv_bfloat16 *pxhl, *pW1hl, *pW2hl, *pfchl, *ppjhl, *pAhl, *pL1hl, *pHhl;
    cudaGetSymbolAddress((void**)&pX,    g_X);
    cudaGetSymbolAddress((void**)&pWsm,  g_Wsm);
    cudaGetSymbolAddress((void**)&pA,    g_A);
    cudaGetSymbolAddress((void**)&pR1,   g_R1);
    cudaGetSymbolAddress((void**)&pLN1,  g_LN1);
    cudaGetSymbolAddress((void**)&pR2,   g_R2);
    cudaGetSymbolAddress((void**)&pxhl,  g_xhl);
    cudaGetSymbolAddress((void**)&pW1hl, g_W1hl);
    cudaGetSymbolAddress((void**)&pW2hl, g_W2hl);
    cudaGetSymbolAddress((void**)&pfchl, g_fchl);
    cudaGetSymbolAddress((void**)&ppjhl, g_pjhl);
    cudaGetSymbolAddress((void**)&pAhl,  g_Ahl);
    cudaGetSymbolAddress((void**)&pL1hl, g_L1hl);
    cudaGetSymbolAddress((void**)&pHhl,  g_Hhl);

    cudaFuncSetAttribute(mma_gemm<false,false,false>, cudaFuncAttributeMaxDynamicSharedMemorySize, TCG_SMEM);
    cudaFuncSetAttribute(mma_gemm<false,true ,false>, cudaFuncAttributeMaxDynamicSharedMemorySize, TCG_SMEM);
    cudaFuncSetAttribute(mma_gemm<true ,false,true >, cudaFuncAttributeMaxDynamicSharedMemorySize, TCG_SMEM);

    const long long nLN = (long long)MTOK * D_;

    // 0) conversions to hi/lo bf16
    convert_hl<<<4096, 256>>>(x,      pxhl,  (long long)MTOK * D_, 11);
    convert_hl<<<4096, 256>>>(W1_w,   pW1hl, (long long)D3_  * D_, 11);
    convert_hl<<<2048, 256>>>(W2_w,   pW2hl, (long long)D_   * D_, 11);
    convert_hl<<<4096, 256>>>(fc_w,   pfchl, (long long)DFF_ * D_, 11);
    convert_hl<<<4096, 256>>>(proj_w, ppjhl, (long long)D_ * DFF_, 13);

    // 1) QKV: g_X = x @ W1^T + b          [8192,6144]
    mma_gemm<false,false,false><<<dim3(D3_/128, MTOK/128), 256, TCG_SMEM>>>(
        pxhl, pW1hl, D_, W1_b, nullptr, pX, nullptr, D3_);

    // 2-3) gram + softmax
    attn_gram_kernel<<<dim3(64, 8), 256>>>();
    softmax_kernel<<<64 * DH_, 128>>>();

    // 4) A = w @ V^T (SIMT, K=128), then hi/lo
    wvT_kernel<<<dim3(D_/BN, 1, 64), 256>>>(pWsm, pX, pA);
    convert_hl<<<4096, 256>>>(pA, pAhl, (long long)MTOK * D_, 11);

    // 5) R1 = A @ W2^T + b + x
    mma_gemm<false,true,false><<<dim3(D_/128, MTOK/128), 256, TCG_SMEM>>>(
        pAhl, pW2hl, D_, W2_b, x, pR1, nullptr, D_);

    // 6) LN1
    reduce1_kernel<<<1024, 256>>>(pR1, nLN);
    reduce2_kernel<<<1, 256>>>((double)nLN);
    ln_apply_kernel<<<8192, 256>>>(pR1, ln1_w, ln1_b, pLN1, nLN);
    convert_hl<<<4096, 256>>>(pLN1, pL1hl, nLN, 11);

    // 7) Hhl = hi/lo(gelu(LN1 @ fc^T + b))   [8192,8192] (bf16 written directly)
    mma_gemm<true,false,true><<<dim3(DFF_/128, MTOK/128), 256, TCG_SMEM>>>(
        pL1hl, pfchl, D_, fc_b, nullptr, nullptr, pHhl, DFF_);

    // 8) R2 = H @ proj^T + b + LN1
    mma_gemm<false,true,false><<<dim3(D_/128, MTOK/128), 256, TCG_SMEM>>>(
        pHhl, ppjhl, DFF_, proj_b, pLN1, pR2, nullptr, D_);

    // 9) LN2 -> out
    reduce1_kernel<<<1024, 256>>>(pR2, nLN);
    reduce2_kernel<<<1, 256>>>((double)nLN);
    ln_apply_kernel<<<8192, 256>>>(pR2, ln2_w, ln2_b, out, nLN);
}